// round 14
// baseline (speedup 1.0000x reference)
#include <cuda_runtime.h>
#include <cuda_fp16.h>
#include <math.h>
#include <stdint.h>

constexpr int CB  = 2048;
constexpr int CN  = 64;
constexpr int CE  = 126;
constexpr int CD  = 128;
constexpr int CED = 32;
constexpr int CF  = 2048;

constexpr size_t MN = (size_t)CB * CN;      // 131072
constexpr size_t ME = (size_t)CB * CE;      // 258048

constexpr size_t SZ_NORMED = MN * CD;
constexpr size_t SZ_AGG    = MN * CED;
constexpr size_t SZ_RUC    = MN * CD;

// fp32 scratch
__device__ float g_normed[SZ_NORMED];
__device__ float g_agg   [SZ_AGG];
__device__ float g_counts[CN];
__device__ float g_u     [SZ_RUC];
__device__ float g_x     [SZ_RUC];
// fp16 scratch
__device__ __half g_normed_h[SZ_NORMED];
__device__ __half g_r_h    [SZ_RUC];
__device__ __half g_n2_h   [SZ_RUC];
__device__ __half g_ea_h   [ME * CED];
// fp16 pre-transposed weights [n][k]
__device__ __half g_w1t [2048 * 128];
__device__ __half g_w2t [128 * 2048];
__device__ __half g_ew1t[128 * 288];
__device__ __half g_ew2t[32 * 128];
__device__ __half g_rwt [128 * 256];
__device__ __half g_uwt [128 * 256];
__device__ __half g_cwt [128 * 256];
__device__ __half g_pwt [128 * 32];

// ---------------------------------------------------------------------------
// Prep kernels
// ---------------------------------------------------------------------------
// Tiled transpose fp32 [R][C] -> fp16 [C][R]. R, C multiples of 32.
__global__ void tr_h(const float* __restrict__ src, __half* __restrict__ dst,
                     int R, int C)
{
    __shared__ __half t[32][40];
    int cb = blockIdx.x * 32, rb = blockIdx.y * 32;
    int tx = threadIdx.x, ty = threadIdx.y;   // 32 x 8
#pragma unroll
    for (int i = 0; i < 4; i++) {
        int r = rb + ty + i * 8;
        t[ty + i * 8][tx] = __float2half(src[(size_t)r * C + cb + tx]);
    }
    __syncthreads();
#pragma unroll
    for (int i = 0; i < 4; i++) {
        int c = cb + ty + i * 8;
        dst[(size_t)c * R + rb + tx] = t[tx][ty + i * 8];
    }
}

__global__ void cvt_h8(const float* __restrict__ s, __half* __restrict__ d,
                       size_t n8)
{
    size_t i = (size_t)blockIdx.x * blockDim.x + threadIdx.x;
    if (i >= n8) return;
    size_t b = i * 8;
    float4 v0 = *reinterpret_cast<const float4*>(&s[b]);
    float4 v1 = *reinterpret_cast<const float4*>(&s[b + 4]);
    __half2* dp = reinterpret_cast<__half2*>(&d[b]);
    dp[0] = __floats2half2_rn(v0.x, v0.y);
    dp[1] = __floats2half2_rn(v0.z, v0.w);
    dp[2] = __floats2half2_rn(v1.x, v1.y);
    dp[3] = __floats2half2_rn(v1.z, v1.w);
}

// ---------------------------------------------------------------------------
// fp16 m16n8k16 mma helpers
// ---------------------------------------------------------------------------
__device__ __forceinline__ void mma_f16(float* d, const uint32_t (&a)[4],
                                        const uint32_t (&b)[2])
{
    asm volatile(
        "mma.sync.aligned.m16n8k16.row.col.f32.f16.f16.f32 "
        "{%0,%1,%2,%3},{%4,%5,%6,%7},{%8,%9},{%0,%1,%2,%3};"
        : "+f"(d[0]), "+f"(d[1]), "+f"(d[2]), "+f"(d[3])
        : "r"(a[0]), "r"(a[1]), "r"(a[2]), "r"(a[3]), "r"(b[0]), "r"(b[1]));
}

__device__ __forceinline__ void lda_h(uint32_t (&a)[4], const __half* A, int S,
                                      int m0, int kb, int lane)
{
    int r = m0 + (lane >> 2);
    int c = kb + (lane & 3) * 2;
    a[0] = *reinterpret_cast<const uint32_t*>(&A[r * S + c]);
    a[1] = *reinterpret_cast<const uint32_t*>(&A[(r + 8) * S + c]);
    a[2] = *reinterpret_cast<const uint32_t*>(&A[r * S + c + 8]);
    a[3] = *reinterpret_cast<const uint32_t*>(&A[(r + 8) * S + c + 8]);
}

__device__ __forceinline__ void ldb_h(uint32_t (&b)[2], const __half* W, int S,
                                      int nb, int kb, int lane)
{
    int n = nb + (lane >> 2);
    int c = kb + (lane & 3) * 2;
    b[0] = *reinterpret_cast<const uint32_t*>(&W[n * S + c]);
    b[1] = *reinterpret_cast<const uint32_t*>(&W[n * S + c + 8]);
}

__device__ __forceinline__ void mma_k16_n16(float* d0, float* d1,
    const uint32_t (&a)[4], const __half* W, int S, int nb, int kb, int lane)
{
    uint32_t b[2];
    ldb_h(b, W, S, nb, kb, lane);     mma_f16(d0, a, b);
    ldb_h(b, W, S, nb + 8, kb, lane); mma_f16(d1, a, b);
}

__device__ __forceinline__ void mma_k16_n16_m32(float* d00, float* d01,
    float* d10, float* d11,
    const uint32_t (&a0)[4], const uint32_t (&a1)[4],
    const __half* W, int S, int nb, int kb, int lane)
{
    uint32_t b[2];
    ldb_h(b, W, S, nb, kb, lane);     mma_f16(d00, a0, b); mma_f16(d10, a1, b);
    ldb_h(b, W, S, nb + 8, kb, lane); mma_f16(d01, a0, b); mma_f16(d11, a1, b);
}

__device__ __forceinline__ float gelu_f(float v) {
    return 0.5f * v * (1.f + erff(v * 0.70710678118654752f));
}

// ---------------------------------------------------------------------------
// fp16 fused FFN (unchanged from R12)
// ---------------------------------------------------------------------------
constexpr int F_S = 136;
constexpr size_t FFN_SMEM = (size_t)3 * 128 * F_S * 2;      // 104,448 B

__global__ void __launch_bounds__(512) ffn_tc_k(
    const __half* __restrict__ n2h, const __half* __restrict__ w1t,
    const float* __restrict__ b1, const __half* __restrict__ w2t,
    const float* __restrict__ b2, const float* __restrict__ xres,
    float* __restrict__ out)
{
    extern __shared__ __half sh[];
    __half* Af = sh;
    __half* Hf = Af + 128 * F_S;
    __half* Wf = Hf + 128 * F_S;

    const int tid  = threadIdx.x;
    const int lane = tid & 31;
    const int wrp  = tid >> 5;
    const int m0   = (wrp & 3) * 32;
    const int n0   = (wrp >> 2) * 32;
    const size_t rowBase = (size_t)blockIdx.x * 128;

#pragma unroll
    for (int i = 0; i < 4; i++) {
        int p = tid + 512 * i;
        int r = p >> 4, c4 = p & 15;
        *reinterpret_cast<uint4*>(&Af[r * F_S + c4 * 8]) =
            *reinterpret_cast<const uint4*>(&n2h[(rowBase + r) * 128 + c4 * 8]);
    }

    float acc2[32];
#pragma unroll
    for (int i = 0; i < 32; i++) acc2[i] = 0.f;

    __syncthreads();

    for (int ch = 0; ch < 16; ch++) {
#pragma unroll
        for (int i = 0; i < 4; i++) {
            int p = tid + 512 * i;
            int n = p >> 4, c4 = p & 15;
            *reinterpret_cast<uint4*>(&Wf[n * F_S + c4 * 8]) =
                *reinterpret_cast<const uint4*>(
                    &w1t[(size_t)(ch * 128 + n) * 128 + c4 * 8]);
        }
        __syncthreads();

        float acc1[32];
#pragma unroll
        for (int i = 0; i < 32; i++) acc1[i] = 0.f;

#pragma unroll
        for (int ks = 0; ks < 8; ks++) {
            int kb = ks * 16;
            uint32_t a0[4], a1[4];
            lda_h(a0, Af, F_S, m0,      kb, lane);
            lda_h(a1, Af, F_S, m0 + 16, kb, lane);
#pragma unroll
            for (int nt = 0; nt < 2; nt++) {
                mma_k16_n16_m32(&acc1[(nt*2+0)*4], &acc1[(nt*2+1)*4],
                                &acc1[(4+nt*2+0)*4], &acc1[(4+nt*2+1)*4],
                                a0, a1, Wf, F_S, n0 + nt * 16, kb, lane);
            }
        }

        {
            int r0 = lane >> 2;
#pragma unroll
            for (int mh = 0; mh < 2; mh++)
#pragma unroll
            for (int j = 0; j < 4; j++) {
                int col = n0 + j * 8 + 2 * (lane & 3);
                float bb0 = b1[ch * 128 + col];
                float bb1 = b1[ch * 128 + col + 1];
#pragma unroll
                for (int half = 0; half < 2; half++) {
                    int r = m0 + mh * 16 + r0 + half * 8;
                    float v0 = gelu_f(acc1[(mh*4+j)*4 + half*2 + 0] + bb0);
                    float v1 = gelu_f(acc1[(mh*4+j)*4 + half*2 + 1] + bb1);
                    *reinterpret_cast<__half2*>(&Hf[r * F_S + col]) =
                        __floats2half2_rn(v0, v1);
                }
            }
        }
        __syncthreads();

#pragma unroll
        for (int i = 0; i < 4; i++) {
            int p = tid + 512 * i;
            int n = p >> 4, c4 = p & 15;
            *reinterpret_cast<uint4*>(&Wf[n * F_S + c4 * 8]) =
                *reinterpret_cast<const uint4*>(
                    &w2t[(size_t)n * 2048 + ch * 128 + c4 * 8]);
        }
        __syncthreads();

#pragma unroll
        for (int ks = 0; ks < 8; ks++) {
            int kb = ks * 16;
            uint32_t a0[4], a1[4];
            lda_h(a0, Hf, F_S, m0,      kb, lane);
            lda_h(a1, Hf, F_S, m0 + 16, kb, lane);
#pragma unroll
            for (int nt = 0; nt < 2; nt++) {
                mma_k16_n16_m32(&acc2[(nt*2+0)*4], &acc2[(nt*2+1)*4],
                                &acc2[(4+nt*2+0)*4], &acc2[(4+nt*2+1)*4],
                                a0, a1, Wf, F_S, n0 + nt * 16, kb, lane);
            }
        }
        __syncthreads();
    }

    {
        int r0 = lane >> 2;
#pragma unroll
        for (int mh = 0; mh < 2; mh++)
#pragma unroll
        for (int j = 0; j < 4; j++) {
            int col = n0 + j * 8 + 2 * (lane & 3);
            float bb0 = b2[col], bb1 = b2[col + 1];
#pragma unroll
            for (int half = 0; half < 2; half++) {
                size_t r = rowBase + m0 + mh * 16 + r0 + half * 8;
                float2 xr = *reinterpret_cast<const float2*>(&xres[r * 128 + col]);
                float2 o;
                o.x = acc2[(mh*4+j)*4 + half*2 + 0] + bb0 + xr.x;
                o.y = acc2[(mh*4+j)*4 + half*2 + 1] + bb1 + xr.y;
                *reinterpret_cast<float2*>(&out[r * 128 + col]) = o;
            }
        }
    }
}

// ---------------------------------------------------------------------------
// fp16 fused edge pipeline (unchanged from R12)
// ---------------------------------------------------------------------------
constexpr int E_AS = 104;
constexpr int E_HS = 136;
constexpr size_t EDGE_SMEM = (size_t)(2 * 128 * E_AS) * 2;   // 53,248 B

__global__ void __launch_bounds__(512) edge_tc_k(
    const __half* __restrict__ nrm_h, const __half* __restrict__ ea_h,
    const int* __restrict__ srcI, const int* __restrict__ tgtI,
    const __half* __restrict__ ew1t, const float* __restrict__ e_b1,
    const __half* __restrict__ ew2t, const float* __restrict__ e_b2,
    const float* __restrict__ mask,
    float* __restrict__ msgs_out, float* __restrict__ agg)
{
    extern __shared__ __half she[];
    __half* Af = she;
    __half* Wf = Af + 128 * E_AS;
    __half* Hf  = she;
    __half* W2f = Hf + 128 * E_HS;

    __shared__ int   srcb[128], tgtb[128], tgtn[128];
    __shared__ float mks[128];

    const int tid  = threadIdx.x;
    const int lane = tid & 31;
    const int wrp  = tid >> 5;
    const int wm   = wrp & 7;
    const int wn   = wrp >> 3;
    const int m0   = wm * 16;
    const size_t rowBase = (size_t)blockIdx.x * 128;

    if (tid < 128) {
        size_t row = rowBase + tid;
        int b = (int)(row / CE);
        int e = (int)(row - (size_t)b * CE);
        srcb[tid] = (b * CN + srcI[e]) * CD;
        tgtb[tid] = (b * CN + tgtI[e]) * CD;
        tgtn[tid] = b * CN + tgtI[e];
        mks[tid]  = mask[row];
    }
    __syncthreads();

    float acc1[32];
#pragma unroll
    for (int i = 0; i < 32; i++) acc1[i] = 0.f;

    for (int ch = 0; ch < 3; ch++) {
        const int k0 = ch * 96;
#pragma unroll
        for (int i = 0; i < 3; i++) {
            int p = tid + 512 * i;
            int r = p / 12, j = p % 12;
            int gk = k0 + j * 8;
            uint4 v;
            if (gk < 128)
                v = *reinterpret_cast<const uint4*>(&nrm_h[srcb[r] + gk]);
            else if (gk < 256)
                v = *reinterpret_cast<const uint4*>(&nrm_h[tgtb[r] + gk - 128]);
            else
                v = *reinterpret_cast<const uint4*>(
                        &ea_h[(rowBase + r) * CED + gk - 256]);
            *reinterpret_cast<uint4*>(&Af[r * E_AS + j * 8]) = v;
        }
#pragma unroll
        for (int i = 0; i < 3; i++) {
            int p = tid + 512 * i;
            int n = p / 12, j = p % 12;
            *reinterpret_cast<uint4*>(&Wf[n * E_AS + j * 8]) =
                *reinterpret_cast<const uint4*>(&ew1t[(size_t)n * 288 + k0 + j * 8]);
        }
        __syncthreads();
#pragma unroll
        for (int ks = 0; ks < 6; ks++) {
            int kb = ks * 16;
            uint32_t a[4];
            lda_h(a, Af, E_AS, m0, kb, lane);
#pragma unroll
            for (int g = 0; g < 4; g++) {
                mma_k16_n16(&acc1[(g*2+0)*4], &acc1[(g*2+1)*4],
                            a, Wf, E_AS, wn * 64 + g * 16, kb, lane);
            }
        }
        __syncthreads();
    }

    {
        int r0 = m0 + (lane >> 2);
#pragma unroll
        for (int t = 0; t < 8; t++) {
            int col = wn * 64 + t * 8 + 2 * (lane & 3);
            float bb0 = e_b1[col], bb1 = e_b1[col + 1];
#pragma unroll
            for (int half = 0; half < 2; half++) {
                int r = r0 + half * 8;
                float v0 = fmaxf(acc1[t * 4 + half * 2 + 0] + bb0, 0.f);
                float v1 = fmaxf(acc1[t * 4 + half * 2 + 1] + bb1, 0.f);
                *reinterpret_cast<__half2*>(&Hf[r * E_HS + col]) =
                    __floats2half2_rn(v0, v1);
            }
        }
    }
    {
        int n = tid >> 4, c4 = tid & 15;
        *reinterpret_cast<uint4*>(&W2f[n * E_HS + c4 * 8]) =
            *reinterpret_cast<const uint4*>(&ew2t[(size_t)n * 128 + c4 * 8]);
    }
    __syncthreads();

    float acc2[8];
#pragma unroll
    for (int i = 0; i < 8; i++) acc2[i] = 0.f;
#pragma unroll
    for (int ks = 0; ks < 8; ks++) {
        int kb = ks * 16;
        uint32_t a[4];
        lda_h(a, Hf, E_HS, m0, kb, lane);
        mma_k16_n16(&acc2[0], &acc2[4], a, W2f, E_HS, wn * 16, kb, lane);
    }

    {
        int r0 = m0 + (lane >> 2);
#pragma unroll
        for (int t = 0; t < 2; t++) {
            int col = wn * 16 + t * 8 + 2 * (lane & 3);
            float bb0 = e_b2[col], bb1 = e_b2[col + 1];
#pragma unroll
            for (int half = 0; half < 2; half++) {
                int r = r0 + half * 8;
                float mk = mks[r];
                float v0 = (acc2[t * 4 + half * 2 + 0] + bb0) * mk;
                float v1 = (acc2[t * 4 + half * 2 + 1] + bb1) * mk;
                size_t be = rowBase + r;
                msgs_out[be * 32 + col]     = v0;
                msgs_out[be * 32 + col + 1] = v1;
                float* ap = &agg[(size_t)tgtn[r] * CED + col];
                atomicAdd(ap, v0);
                atomicAdd(ap + 1, v1);
            }
        }
    }
}

// ---------------------------------------------------------------------------
// fp16 GRU GEMMs with fused proj pre-pass (proj never hits HBM).
// RU: outputs r (half) + u (float). !RU: cand + GRU combine + LN2.
// ---------------------------------------------------------------------------
constexpr int G_AS = 264;
constexpr int G_WS = 136;
constexpr int P_S  = 40;    // Aa/PW stride (halfs); 20 words -> conflict-free
constexpr size_t GRU_SMEM = (size_t)(128 * G_AS + 128 * G_WS) * 2;  // 102,400 B

template<bool RU>
__global__ void __launch_bounds__(512) gru_tc_k(
    const __half* __restrict__ a1h, const __half* __restrict__ rh,
    const float* __restrict__ agg, const float* __restrict__ counts,
    const __half* __restrict__ pwt, const float* __restrict__ proj_b,
    const __half* __restrict__ w0t, const float* __restrict__ b0p,
    const __half* __restrict__ w1t_, const float* __restrict__ b1p,
    void* out0v, void* out1v,
    const float* __restrict__ uu, const float* __restrict__ nfp,
    const float* __restrict__ nrm32,
    const float* __restrict__ g2, const float* __restrict__ bb2)
{
    extern __shared__ __half shg[];
    __half* Af = shg;                 // [128][264]
    __half* Wf = Af + 128 * G_AS;     // [128][136]; pre-pass aliases Aa/PW here
    __half* Aa = Wf;                  // [128][40]
    __half* PW = Wf + 128 * P_S;      // [128][40]
    __shared__ float rcnt_s[64];

    const int tid  = threadIdx.x;
    const int lane = tid & 31;
    const int wrp  = tid >> 5;
    const int wm   = wrp & 7;
    const int wn   = wrp >> 3;
    const int m0   = wm * 16;
    const size_t rowBase = (size_t)blockIdx.x * 128;

    // Af first half: [normed] (or [r*normed])
#pragma unroll
    for (int i = 0; i < 4; i++) {
        int p = tid + 512 * i;
        int r = p >> 4, q = p & 15;
        uint4 v = *reinterpret_cast<const uint4*>(&a1h[(rowBase + r) * 128 + q * 8]);
        if (!RU) {
            uint4 rv = *reinterpret_cast<const uint4*>(&rh[(rowBase + r) * 128 + q * 8]);
            __half2* vp = reinterpret_cast<__half2*>(&v);
            const __half2* rp = reinterpret_cast<const __half2*>(&rv);
            vp[0] = __hmul2(vp[0], rp[0]);
            vp[1] = __hmul2(vp[1], rp[1]);
            vp[2] = __hmul2(vp[2], rp[2]);
            vp[3] = __hmul2(vp[3], rp[3]);
        }
        *reinterpret_cast<uint4*>(&Af[r * G_AS + q * 8]) = v;
    }
    if (tid < 64) rcnt_s[tid] = 1.f / fmaxf(counts[tid], 1.f);
    __syncthreads();

    // Aa = agg * rcnt (fp16), PW = proj_w^T
#pragma unroll
    for (int i = 0; i < 8; i++) {
        int p = tid + 512 * i;
        int r = p >> 5, c = p & 31;
        Aa[r * P_S + c] =
            __float2half(agg[(rowBase + r) * 32 + c] * rcnt_s[r & 63]);
    }
#pragma unroll
    for (int i = 0; i < 8; i++) {
        int p = tid + 512 * i;
        int n = p >> 5, k = p & 31;
        PW[n * P_S + k] = pwt[n * 32 + k];
    }
    __syncthreads();

    // proj pre-pass: proj(128x128) = Aa @ PW^T, K=32 -> Af second half
    {
        float accp[32];
#pragma unroll
        for (int i = 0; i < 32; i++) accp[i] = 0.f;
#pragma unroll
        for (int ks = 0; ks < 2; ks++) {
            int kb = ks * 16;
            uint32_t a[4];
            lda_h(a, Aa, P_S, m0, kb, lane);
#pragma unroll
            for (int g = 0; g < 4; g++) {
                mma_k16_n16(&accp[(g*2+0)*4], &accp[(g*2+1)*4],
                            a, PW, P_S, wn * 64 + g * 16, kb, lane);
            }
        }
        int r0 = m0 + (lane >> 2);
#pragma unroll
        for (int t = 0; t < 8; t++) {
            int col = wn * 64 + t * 8 + 2 * (lane & 3);
            float pb0 = proj_b[col], pb1 = proj_b[col + 1];
#pragma unroll
            for (int half = 0; half < 2; half++) {
                int r = r0 + half * 8;
                float v0 = accp[t * 4 + half * 2 + 0] + pb0;
                float v1 = accp[t * 4 + half * 2 + 1] + pb1;
                *reinterpret_cast<__half2*>(&Af[r * G_AS + 128 + col]) =
                    __floats2half2_rn(v0, v1);
            }
        }
    }
    __syncthreads();

    constexpr int NW = RU ? 2 : 1;
    float acc[NW][32];
#pragma unroll
    for (int s = 0; s < NW; s++)
#pragma unroll
        for (int i = 0; i < 32; i++) acc[s][i] = 0.f;

    for (int ws = 0; ws < NW; ws++) {
        const __half* wt = (ws == 0) ? w0t : w1t_;
        for (int kc = 0; kc < 2; kc++) {
#pragma unroll
            for (int i = 0; i < 4; i++) {
                int p = tid + 512 * i;
                int n = p >> 4, c4 = p & 15;
                *reinterpret_cast<uint4*>(&Wf[n * G_WS + c4 * 8]) =
                    *reinterpret_cast<const uint4*>(
                        &wt[(size_t)n * 256 + kc * 128 + c4 * 8]);
            }
            __syncthreads();
#pragma unroll
            for (int ks = 0; ks < 8; ks++) {
                int kb = ks * 16;
                uint32_t a[4];
                lda_h(a, Af, G_AS, m0, kc * 128 + kb, lane);
#pragma unroll
                for (int g = 0; g < 4; g++) {
                    mma_k16_n16(&acc[ws][(g*2+0)*4], &acc[ws][(g*2+1)*4],
                                a, Wf, G_WS, wn * 64 + g * 16, kb, lane);
                }
            }
            __syncthreads();
        }
    }

    if (RU) {
        __half* r_out = (__half*)out0v;
        float*  u_out = (float*)out1v;
        int r0 = m0 + (lane >> 2);
#pragma unroll
        for (int t = 0; t < 8; t++) {
            int col = wn * 64 + t * 8 + 2 * (lane & 3);
            float rb0 = b0p[col], rb1 = b0p[col + 1];
            float ub0 = b1p[col], ub1 = b1p[col + 1];
#pragma unroll
            for (int half = 0; half < 2; half++) {
                size_t r = rowBase + r0 + half * 8;
                float rv0 = 1.f / (1.f + expf(-(acc[0][t*4+half*2+0] + rb0)));
                float rv1 = 1.f / (1.f + expf(-(acc[0][t*4+half*2+1] + rb1)));
                float uv0 = 1.f / (1.f + expf(-(acc[1][t*4+half*2+0] + ub0)));
                float uv1 = 1.f / (1.f + expf(-(acc[1][t*4+half*2+1] + ub1)));
                *reinterpret_cast<__half2*>(&r_out[r * 128 + col]) =
                    __floats2half2_rn(rv0, rv1);
                float2 o; o.x = uv0; o.y = uv1;
                *reinterpret_cast<float2*>(&u_out[r * 128 + col]) = o;
            }
        }
    } else {
        float*  x_out  = (float*)out0v;
        __half* n2_out = (__half*)out1v;
        float* X = reinterpret_cast<float*>(shg);   // [128][132] floats
        int r0 = m0 + (lane >> 2);
#pragma unroll
        for (int t = 0; t < 8; t++) {
            int col = wn * 64 + t * 8 + 2 * (lane & 3);
            float bb0 = b0p[col], bb1 = b0p[col + 1];
#pragma unroll
            for (int half = 0; half < 2; half++) {
                int rl = r0 + half * 8;
                size_t gi = (rowBase + rl) * 128 + col;
                float c0 = tanhf(acc[0][t*4+half*2+0] + bb0);
                float c1 = tanhf(acc[0][t*4+half*2+1] + bb1);
                float2 uv  = *reinterpret_cast<const float2*>(&uu[gi]);
                float2 nv  = *reinterpret_cast<const float2*>(&nrm32[gi]);
                float2 nfv = *reinterpret_cast<const float2*>(&nfp[gi]);
                float x0 = nfv.x + (1.f - uv.x) * nv.x + uv.x * c0;
                float x1 = nfv.y + (1.f - uv.y) * nv.y + uv.y * c1;
                float2 xo; xo.x = x0; xo.y = x1;
                *reinterpret_cast<float2*>(&x_out[gi]) = xo;
                *reinterpret_cast<float2*>(&X[rl * 132 + col]) = xo;
            }
        }
        __syncthreads();
        {
            int row = tid >> 2, q = tid & 3;
            float vals[32];
            float s = 0.f;
#pragma unroll
            for (int i4 = 0; i4 < 8; i4++) {
                float4 v = *reinterpret_cast<const float4*>(&X[row * 132 + q * 32 + i4 * 4]);
                vals[i4*4+0] = v.x; vals[i4*4+1] = v.y;
                vals[i4*4+2] = v.z; vals[i4*4+3] = v.w;
                s += v.x + v.y + v.z + v.w;
            }
            s += __shfl_xor_sync(~0u, s, 1);
            s += __shfl_xor_sync(~0u, s, 2);
            float mean = s * (1.f / 128.f);
            float sq = 0.f;
#pragma unroll
            for (int i = 0; i < 32; i++) {
                float d = vals[i] - mean;
                sq += d * d;
            }
            sq += __shfl_xor_sync(~0u, sq, 1);
            sq += __shfl_xor_sync(~0u, sq, 2);
            float kq = rsqrtf(sq * (1.f / 128.f) + 1e-5f);
            size_t r = rowBase + row;
#pragma unroll
            for (int i4 = 0; i4 < 8; i4++) {
                int c0 = q * 32 + i4 * 4;
                float4 g4 = *reinterpret_cast<const float4*>(&g2[c0]);
                float4 b4 = *reinterpret_cast<const float4*>(&bb2[c0]);
                float o0 = (vals[i4*4+0] - mean) * kq * g4.x + b4.x;
                float o1 = (vals[i4*4+1] - mean) * kq * g4.y + b4.y;
                float o2 = (vals[i4*4+2] - mean) * kq * g4.z + b4.z;
                float o3 = (vals[i4*4+3] - mean) * kq * g4.w + b4.w;
                __half2* np = reinterpret_cast<__half2*>(&n2_out[r * 128 + c0]);
                np[0] = __floats2half2_rn(o0, o1);
                np[1] = __floats2half2_rn(o2, o3);
            }
        }
    }
}

// ---------------------------------------------------------------------------
// LN1 (dual fp32 + fp16 output) + fused counts (block 0)
// ---------------------------------------------------------------------------
__global__ void ln_k(const float* __restrict__ in, const float* __restrict__ g,
                     const float* __restrict__ bb, float* __restrict__ out,
                     __half* __restrict__ out_h,
                     const int* __restrict__ tgt, float* __restrict__ counts)
{
    if (blockIdx.x == 0 && threadIdx.x < CE)
        atomicAdd(&counts[tgt[threadIdx.x]], 1.f);

    const int w = threadIdx.x >> 5;
    const int lane = threadIdx.x & 31;
    const size_t row = (size_t)blockIdx.x * 8 + w;
    float4 v = *reinterpret_cast<const float4*>(&in[row * 128 + lane * 4]);
    float s = v.x + v.y + v.z + v.w;
#pragma unroll
    for (int o = 16; o > 0; o >>= 1) s += __shfl_xor_sync(~0u, s, o);
    float mean = s * (1.f / 128.f);
    float dx = v.x - mean, dy = v.y - mean, dz = v.z - mean, dw = v.w - mean;
    float q = dx * dx + dy * dy + dz * dz + dw * dw;
#pragma unroll
    for (int o = 16; o > 0; o >>= 1) q += __shfl_xor_sync(~0u, q, o);
    float kq = rsqrtf(q * (1.f / 128.f) + 1e-5f);
    float4 g4 = *reinterpret_cast<const float4*>(&g[lane * 4]);
    float4 b4 = *reinterpret_cast<const float4*>(&bb[lane * 4]);
    float o0 = dx * kq * g4.x + b4.x;
    float o1 = dy * kq * g4.y + b4.y;
    float o2 = dz * kq * g4.z + b4.z;
    float o3 = dw * kq * g4.w + b4.w;
    float4 o; o.x = o0; o.y = o1; o.z = o2; o.w = o3;
    *reinterpret_cast<float4*>(&out[row * 128 + lane * 4]) = o;
    __half2* hp = reinterpret_cast<__half2*>(&out_h[row * 128 + lane * 4]);
    hp[0] = __floats2half2_rn(o0, o1);
    hp[1] = __floats2half2_rn(o2, o3);
}

// ---------------------------------------------------------------------------
extern "C" void kernel_launch(void* const* d_in, const int* in_sizes, int n_in,
                              void* d_out, int out_size)
{
    const float* nf        = (const float*)d_in[0];
    const float* edge_attr = (const float*)d_in[1];
    const int*   src       = (const int*)  d_in[2];
    const int*   tgt       = (const int*)  d_in[3];
    const float* mask      = (const float*)d_in[4];
    const float* e_w1   = (const float*)d_in[6];
    const float* e_b1   = (const float*)d_in[7];
    const float* e_w2   = (const float*)d_in[8];
    const float* e_b2   = (const float*)d_in[9];
    const float* proj_w = (const float*)d_in[10];
    const float* proj_b = (const float*)d_in[11];
    const float* r_w    = (const float*)d_in[12];
    const float* r_b    = (const float*)d_in[13];
    const float* u_w    = (const float*)d_in[14];
    const float* u_b    = (const float*)d_in[15];
    const float* c_w    = (const float*)d_in[16];
    const float* c_b    = (const float*)d_in[17];
    const float* n1_g   = (const float*)d_in[18];
    const float* n1_b   = (const float*)d_in[19];
    const float* n2_g   = (const float*)d_in[20];
    const float* n2_b   = (const float*)d_in[21];
    const float* f_w1   = (const float*)d_in[22];
    const float* f_b1   = (const float*)d_in[23];
    const float* f_w2   = (const float*)d_in[24];
    const float* f_b2   = (const float*)d_in[25];

    float* out_x    = (float*)d_out;
    float* out_msgs = out_x + SZ_NORMED;

    float *p_normed, *p_agg, *p_counts, *p_u, *p_x;
    __half *p_nh, *p_rh, *p_n2h, *p_eah;
    __half *p_w1t, *p_w2t, *p_ew1t, *p_ew2t, *p_rwt, *p_uwt, *p_cwt, *p_pwt;
    cudaGetSymbolAddress((void**)&p_normed, g_normed);
    cudaGetSymbolAddress((void**)&p_agg,    g_agg);
    cudaGetSymbolAddress((void**)&p_counts, g_counts);
    cudaGetSymbolAddress((void**)&p_u,      g_u);
    cudaGetSymbolAddress((void**)&p_x,      g_x);
    cudaGetSymbolAddress((void**)&p_nh,     g_normed_h);
    cudaGetSymbolAddress((void**)&p_rh,     g_r_h);
    cudaGetSymbolAddress((void**)&p_n2h,    g_n2_h);
    cudaGetSymbolAddress((void**)&p_eah,    g_ea_h);
    cudaGetSymbolAddress((void**)&p_w1t,    g_w1t);
    cudaGetSymbolAddress((void**)&p_w2t,    g_w2t);
    cudaGetSymbolAddress((void**)&p_ew1t,   g_ew1t);
    cudaGetSymbolAddress((void**)&p_ew2t,   g_ew2t);
    cudaGetSymbolAddress((void**)&p_rwt,    g_rwt);
    cudaGetSymbolAddress((void**)&p_uwt,    g_uwt);
    cudaGetSymbolAddress((void**)&p_cwt,    g_cwt);
    cudaGetSymbolAddress((void**)&p_pwt,    g_pwt);

    cudaFuncSetAttribute(ffn_tc_k,  cudaFuncAttributeMaxDynamicSharedMemorySize, (int)FFN_SMEM);
    cudaFuncSetAttribute(edge_tc_k, cudaFuncAttributeMaxDynamicSharedMemorySize, (int)EDGE_SMEM);
    cudaFuncSetAttribute(gru_tc_k<true>,  cudaFuncAttributeMaxDynamicSharedMemorySize, (int)GRU_SMEM);
    cudaFuncSetAttribute(gru_tc_k<false>, cudaFuncAttributeMaxDynamicSharedMemorySize, (int)GRU_SMEM);

    cudaMemsetAsync(p_agg, 0, SZ_AGG * sizeof(float));
    cudaMemsetAsync(p_counts, 0, CN * sizeof(float));

    // prep: tiled transposes (all dims multiples of 32) + edge_attr cvt
    dim3 tb(32, 8);
    tr_h<<<dim3(64, 4),  tb>>>(f_w1,   p_w1t,  128, 2048);
    tr_h<<<dim3(4, 64),  tb>>>(f_w2,   p_w2t,  2048, 128);
    tr_h<<<dim3(4, 9),   tb>>>(e_w1,   p_ew1t, 288, 128);
    tr_h<<<dim3(1, 4),   tb>>>(e_w2,   p_ew2t, 128, 32);
    tr_h<<<dim3(4, 8),   tb>>>(r_w,    p_rwt,  256, 128);
    tr_h<<<dim3(4, 8),   tb>>>(u_w,    p_uwt,  256, 128);
    tr_h<<<dim3(4, 8),   tb>>>(c_w,    p_cwt,  256, 128);
    tr_h<<<dim3(4, 1),   tb>>>(proj_w, p_pwt,  32, 128);
    cvt_h8<<<(unsigned)((ME * CED / 8 + 255) / 256), 256>>>(edge_attr, p_eah, ME * CED / 8);

    // 1. LN1 + counts
    ln_k<<<(unsigned)(MN / 8), 256>>>(nf, n1_g, n1_b, p_normed, p_nh, tgt, p_counts);

    // 2. edge pipeline
    edge_tc_k<<<(unsigned)(ME / 128), 512, EDGE_SMEM>>>(
        p_nh, p_eah, src, tgt, p_ew1t, e_b1, p_ew2t, e_b2, mask,
        out_msgs, p_agg);

    // 3. r (fp16), u (fp32)  [proj fused]
    gru_tc_k<true><<<(unsigned)(MN / 128), 512, GRU_SMEM>>>(
        p_nh, nullptr, p_agg, p_counts, p_pwt, proj_b,
        p_rwt, r_b, p_uwt, u_b, p_rh, p_u,
        nullptr, nullptr, nullptr, nullptr, nullptr);

    // 4. cand + GRU combine + LN2 -> x (fp32), n2 (fp16)  [proj fused]
    gru_tc_k<false><<<(unsigned)(MN / 128), 512, GRU_SMEM>>>(
        p_nh, p_rh, p_agg, p_counts, p_pwt, proj_b,
        p_cwt, c_b, nullptr, nullptr, p_x, p_n2h,
        p_u, nf, p_normed, n2_g, n2_b);

    // 5. fused FFN
    ffn_tc_k<<<(unsigned)(MN / 128), 512, FFN_SMEM>>>(
        p_n2h, p_w1t, f_b1, p_w2t, f_b2, p_x, out_x);
}